// round 1
// baseline (speedup 1.0000x reference)
#include <cuda_runtime.h>

#define NN 2000000
#define DD 128
#define BB 1024
#define STEPS 3

// ---------------- device scratch (no allocs allowed) ----------------
__device__ int   g_is64;
__device__ int   g_off[BB + 1];
__device__ float g_h[BB * DD];
__device__ float g_c[BB * DD];
__device__ float g_r[BB * DD];
__device__ float g_gates[BB * 4 * DD];
__device__ float g_Weff[4 * DD * 2 * DD];  // 512 x 256
__device__ float g_bias[4 * DD];

// ---------------- dtype detection for batch_index ----------------
// If data is int64 (values < 2^31), every odd int32 position is a zero high
// word. If int32 (sorted 0..B-1), v[N-1] ~ 1023 and mid odd positions ~ 512.
__global__ void detect_kernel(const int* __restrict__ v) {
    g_is64 = (v[NN - 1] == 0 && v[(NN / 2) | 1] == 0 && v[(NN / 4) | 1] == 0) ? 1 : 0;
}

__device__ __forceinline__ int load_bi(const void* bi, int i, int is64) {
    if (is64) return (int)((const long long*)bi)[i];
    return ((const int*)bi)[i];
}

// ---------------- weight fold + bias fold ----------------
// q_star = [h_prev, r_prev], LSTM input = q_star @ W_ih^T + h_prev @ W_hh^T
// => gates = [h_prev, r_prev] @ Weff^T + (b_ih + b_hh)
// Weff[:,0:128] = W_ih[:,0:128] + W_hh ;  Weff[:,128:256] = W_ih[:,128:256]
__global__ void prep_kernel(const float* __restrict__ W_ih, const float* __restrict__ W_hh,
                            const float* __restrict__ b_ih, const float* __restrict__ b_hh) {
    int id = blockIdx.x * blockDim.x + threadIdx.x;  // 131072 threads
    int gg = id >> 8, k = id & 255;
    float w = W_ih[gg * 256 + k];
    if (k < 128) w += W_hh[gg * 128 + k];
    g_Weff[id] = w;
    if (id < 4 * DD) g_bias[id] = b_ih[id] + b_hh[id];
}

__global__ void init_kernel() {
    int id = blockIdx.x * blockDim.x + threadIdx.x;  // 131072 threads
    g_h[id] = 0.f; g_c[id] = 0.f; g_r[id] = 0.f;
}

// ---------------- graph start offsets (batch_index is sorted) ----------------
__global__ void offsets_kernel(const void* __restrict__ bi) {
    int i = blockIdx.x * blockDim.x + threadIdx.x;
    if (i >= NN) return;
    int is64 = g_is64;
    int cur  = load_bi(bi, i, is64);
    int prev = (i == 0) ? -1 : load_bi(bi, i - 1, is64);
    for (int g = prev + 1; g <= cur; ++g) g_off[g] = i;
    if (i == NN - 1)
        for (int g = cur + 1; g <= BB; ++g) g_off[g] = NN;
}

// ---------------- LSTM gates GEMM: gates[B,512] = in[B,256] @ Weff^T + bias ----
// Block: 256 threads, 16 batch rows x 256 gate cols. Grid (64, 2).
__global__ __launch_bounds__(256) void lstm_kernel() {
    __shared__ float s_in[16][256];  // 16 KB
    int row0 = blockIdx.x * 16;
    int gc   = blockIdx.y * 256 + threadIdx.x;
    int k    = threadIdx.x;
    #pragma unroll
    for (int t = 0; t < 16; ++t) {
        float v;
        if (k < 128) v = g_h[(row0 + t) * DD + k];
        else         v = g_r[(row0 + t) * DD + (k - 128)];
        s_in[t][k] = v;
    }
    __syncthreads();

    float acc[16];
    #pragma unroll
    for (int t = 0; t < 16; ++t) acc[t] = 0.f;

    const float4* w4 = (const float4*)(g_Weff + gc * 256);
    #pragma unroll 4
    for (int k4 = 0; k4 < 64; ++k4) {
        float4 w = w4[k4];  // per-thread streaming read, L1/L2 resident
        #pragma unroll
        for (int t = 0; t < 16; ++t) {
            float4 iv = *(const float4*)&s_in[t][k4 * 4];  // smem broadcast
            acc[t] += w.x * iv.x + w.y * iv.y + w.z * iv.z + w.w * iv.w;
        }
    }
    float b = g_bias[gc];
    #pragma unroll
    for (int t = 0; t < 16; ++t)
        g_gates[(row0 + t) * 512 + gc] = acc[t] + b;
}

// ---------------- fused LSTM activation + online-softmax attention pooling ----
// One block per graph. Single pass over this graph's x rows:
//   e = x.q (warp dot), online softmax (m, s) with rescaled pooled r.
__global__ __launch_bounds__(256) void attn_kernel(const float* __restrict__ x,
                                                   float* __restrict__ out,
                                                   int is_last) {
    __shared__ float s_q[128];
    __shared__ float s_r[8][128];
    __shared__ float s_m[8];
    __shared__ float s_s[8];

    int g = blockIdx.x;
    int tid = threadIdx.x;

    // LSTM elementwise: c' = sig(f)*c + sig(i)*tanh(g); h' = sig(o)*tanh(c')
    if (tid < 128) {
        int base = g * 512 + tid;
        float gi = g_gates[base];
        float gf = g_gates[base + 128];
        float gg = g_gates[base + 256];
        float go = g_gates[base + 384];
        float si = 1.f / (1.f + __expf(-gi));
        float sf = 1.f / (1.f + __expf(-gf));
        float so = 1.f / (1.f + __expf(-go));
        float cn = sf * g_c[g * DD + tid] + si * tanhf(gg);
        float hn = so * tanhf(cn);
        g_c[g * DD + tid] = cn;
        g_h[g * DD + tid] = hn;
        s_q[tid] = hn;
    }
    __syncthreads();

    int lane = tid & 31, wid = tid >> 5;
    float4 q4 = ((const float4*)s_q)[lane];  // lane covers dims 4*lane..4*lane+3
    int start = g_off[g], end = g_off[g + 1];
    const float4* x4 = (const float4*)x;

    float m = -3.4e38f;
    float s = 0.f;
    float4 racc = make_float4(0.f, 0.f, 0.f, 0.f);

    // 8 warps x 4-node unroll per iteration => 32 nodes / block-iter
    for (int n0 = start + wid * 4; n0 < end; n0 += 32) {
        float4 xv[4];
        #pragma unroll
        for (int j = 0; j < 4; ++j) {
            int n = n0 + j;
            xv[j] = (n < end) ? x4[n * 32 + lane] : make_float4(0.f, 0.f, 0.f, 0.f);
        }
        #pragma unroll
        for (int j = 0; j < 4; ++j) {
            if (n0 + j < end) {
                float e = xv[j].x * q4.x + xv[j].y * q4.y + xv[j].z * q4.z + xv[j].w * q4.w;
                e += __shfl_xor_sync(0xffffffffu, e, 16);
                e += __shfl_xor_sync(0xffffffffu, e, 8);
                e += __shfl_xor_sync(0xffffffffu, e, 4);
                e += __shfl_xor_sync(0xffffffffu, e, 2);
                e += __shfl_xor_sync(0xffffffffu, e, 1);
                if (e > m) {  // warp-uniform branch
                    float sc = __expf(m - e);
                    s *= sc;
                    racc.x *= sc; racc.y *= sc; racc.z *= sc; racc.w *= sc;
                    m = e;
                }
                float p = __expf(e - m);
                s += p;
                racc.x += p * xv[j].x; racc.y += p * xv[j].y;
                racc.z += p * xv[j].z; racc.w += p * xv[j].w;
            }
        }
    }

    if (lane == 0) { s_m[wid] = m; s_s[wid] = s; }
    ((float4*)s_r[wid])[lane] = racc;
    __syncthreads();

    // combine 8 per-warp partial softmaxes
    if (tid < 128) {
        float M = -3.4e38f;
        #pragma unroll
        for (int w = 0; w < 8; ++w)
            if (s_s[w] > 0.f && s_m[w] > M) M = s_m[w];
        float S = 0.f, rs = 0.f;
        #pragma unroll
        for (int w = 0; w < 8; ++w) {
            if (s_s[w] > 0.f) {
                float sc = __expf(s_m[w] - M);
                S  += s_s[w] * sc;
                rs += s_r[w][tid] * sc;
            }
        }
        float rf = rs / (S + 1e-16f);
        g_r[g * DD + tid] = rf;
        if (is_last) {
            out[g * 2 * DD + tid]      = s_q[tid];  // q
            out[g * 2 * DD + DD + tid] = rf;        // r
        }
    }
}

// ---------------- launch ----------------
extern "C" void kernel_launch(void* const* d_in, const int* in_sizes, int n_in,
                              void* d_out, int out_size) {
    const float* x    = (const float*)d_in[0];
    const void*  bi   = d_in[1];
    const float* W_ih = (const float*)d_in[2];
    const float* W_hh = (const float*)d_in[3];
    const float* b_ih = (const float*)d_in[4];
    const float* b_hh = (const float*)d_in[5];
    float* out = (float*)d_out;

    detect_kernel<<<1, 1>>>((const int*)bi);
    prep_kernel<<<512, 256>>>(W_ih, W_hh, b_ih, b_hh);
    init_kernel<<<512, 256>>>();
    offsets_kernel<<<(NN + 255) / 256, 256>>>(bi);

    for (int step = 0; step < STEPS; ++step) {
        lstm_kernel<<<dim3(64, 2), 256>>>();
        attn_kernel<<<BB, 256>>>(x, out, step == STEPS - 1 ? 1 : 0);
    }
}

// round 2
// speedup vs baseline: 1.0556x; 1.0556x over previous
#include <cuda_runtime.h>

#define NN 2000000
#define DD 128
#define BB 1024
#define STEPS 3
#define CHUNKS 8                 // chunks per graph
#define NPART (BB * CHUNKS)      // 8192 partial slots

// ---------------- device scratch (no allocs allowed) ----------------
__device__ int   g_is64;
__device__ int   g_off[BB + 1];
__device__ float g_h[BB * DD];
__device__ float g_c[BB * DD];
__device__ float g_r[BB * DD];
__device__ float g_gates[BB * 4 * DD];
__device__ float g_Weff[4 * DD * 2 * DD];  // 512 x 256
__device__ float g_bias[4 * DD];
__device__ float g_pm[NPART];              // per-chunk running max
__device__ float g_ps[NPART];              // per-chunk exp-sum
__device__ float g_pr[NPART * DD];         // per-chunk pooled partial (4 MB)

// ---------------- dtype detection for batch_index ----------------
// int64 sorted values < 2^31 => every odd int32 word is 0. int32 sorted
// 0..1023 => last element ~1023, mid odd elements ~512.
__global__ void detect_kernel(const int* __restrict__ v) {
    g_is64 = (v[NN - 1] == 0 && v[(NN / 2) | 1] == 0 && v[(NN / 4) | 1] == 0) ? 1 : 0;
}

__device__ __forceinline__ int load_bi(const void* bi, int i, int is64) {
    if (is64) return (int)((const long long*)bi)[i];
    return ((const int*)bi)[i];
}

// ---------------- weight fold + bias fold ----------------
// gates = [h_prev, r_prev] @ Weff^T + (b_ih + b_hh)
// Weff[:,0:128] = W_ih[:,0:128] + W_hh ; Weff[:,128:256] = W_ih[:,128:256]
__global__ void prep_kernel(const float* __restrict__ W_ih, const float* __restrict__ W_hh,
                            const float* __restrict__ b_ih, const float* __restrict__ b_hh) {
    int id = blockIdx.x * blockDim.x + threadIdx.x;  // 131072 threads
    int gg = id >> 8, k = id & 255;
    float w = W_ih[gg * 256 + k];
    if (k < 128) w += W_hh[gg * 128 + k];
    g_Weff[id] = w;
    if (id < 4 * DD) g_bias[id] = b_ih[id] + b_hh[id];
}

__global__ void init_kernel() {
    int id = blockIdx.x * blockDim.x + threadIdx.x;  // 131072 threads
    g_h[id] = 0.f; g_c[id] = 0.f; g_r[id] = 0.f;
}

// ---------------- graph start offsets (batch_index is sorted) ----------------
__global__ void offsets_kernel(const void* __restrict__ bi) {
    int i = blockIdx.x * blockDim.x + threadIdx.x;
    if (i >= NN) return;
    int is64 = g_is64;
    int cur  = load_bi(bi, i, is64);
    int prev = (i == 0) ? -1 : load_bi(bi, i - 1, is64);
    for (int g = prev + 1; g <= cur; ++g) g_off[g] = i;
    if (i == NN - 1)
        for (int g = cur + 1; g <= BB; ++g) g_off[g] = NN;
}

// ---------------- LSTM gates GEMM: gates[B,512] = in[B,256] @ Weff^T + bias ----
__global__ __launch_bounds__(256) void lstm_kernel() {
    __shared__ float s_in[16][256];  // 16 KB
    int row0 = blockIdx.x * 16;
    int gc   = blockIdx.y * 256 + threadIdx.x;
    int k    = threadIdx.x;
    #pragma unroll
    for (int t = 0; t < 16; ++t) {
        float v;
        if (k < 128) v = g_h[(row0 + t) * DD + k];
        else         v = g_r[(row0 + t) * DD + (k - 128)];
        s_in[t][k] = v;
    }
    __syncthreads();

    float acc[16];
    #pragma unroll
    for (int t = 0; t < 16; ++t) acc[t] = 0.f;

    const float4* w4 = (const float4*)(g_Weff + gc * 256);
    #pragma unroll 4
    for (int k4 = 0; k4 < 64; ++k4) {
        float4 w = w4[k4];
        #pragma unroll
        for (int t = 0; t < 16; ++t) {
            float4 iv = *(const float4*)&s_in[t][k4 * 4];
            acc[t] += w.x * iv.x + w.y * iv.y + w.z * iv.z + w.w * iv.w;
        }
    }
    float b = g_bias[gc];
    #pragma unroll
    for (int t = 0; t < 16; ++t)
        g_gates[(row0 + t) * 512 + gc] = acc[t] + b;
}

// ---------------- LSTM elementwise activation ----------------
__global__ __launch_bounds__(128) void lstm_act_kernel() {
    int g = blockIdx.x, tid = threadIdx.x;
    int base = g * 512 + tid;
    float gi = g_gates[base];
    float gf = g_gates[base + 128];
    float gg = g_gates[base + 256];
    float go = g_gates[base + 384];
    float si = 1.f / (1.f + __expf(-gi));
    float sf = 1.f / (1.f + __expf(-gf));
    float so = 1.f / (1.f + __expf(-go));
    float cn = sf * g_c[g * DD + tid] + si * tanhf(gg);
    float hn = so * tanhf(cn);
    g_c[g * DD + tid] = cn;
    g_h[g * DD + tid] = hn;
}

// ---------------- chunked online-softmax attention pooling (partials) --------
// Grid = BB*CHUNKS blocks. Block b handles chunk (b & 7) of graph (b >> 3).
// Single pass over its node range with online softmax; writes (m, s, r[128]).
__global__ __launch_bounds__(256) void attn_kernel(const float* __restrict__ x) {
    __shared__ float s_q[128];
    __shared__ float s_r[8][128];
    __shared__ float s_m[8];
    __shared__ float s_s[8];

    int b = blockIdx.x;
    int g = b >> 3, cidx = b & 7;
    int tid = threadIdx.x;

    if (tid < 128) s_q[tid] = g_h[g * DD + tid];
    __syncthreads();

    int gs = g_off[g], ge = g_off[g + 1], len = ge - gs;
    int start = gs + (len * cidx) / CHUNKS;
    int end   = gs + (len * (cidx + 1)) / CHUNKS;

    int lane = tid & 31, wid = tid >> 5;
    float4 q4 = ((const float4*)s_q)[lane];
    const float4* x4 = (const float4*)x;

    float m = -3.4e38f;
    float s = 0.f;
    float4 racc = make_float4(0.f, 0.f, 0.f, 0.f);

    // 8 warps x 4-node unroll, double-buffered prefetch (32 nodes/block-iter)
    int n0 = start + wid * 4;
    float4 cur[4];
    if (n0 < end) {
        #pragma unroll
        for (int j = 0; j < 4; ++j)
            cur[j] = (n0 + j < end) ? x4[(n0 + j) * 32 + lane]
                                    : make_float4(0.f, 0.f, 0.f, 0.f);
    }
    for (; n0 < end; n0 += 32) {
        int n1 = n0 + 32;
        float4 nxt[4];
        if (n1 < end) {
            #pragma unroll
            for (int j = 0; j < 4; ++j)
                nxt[j] = (n1 + j < end) ? x4[(n1 + j) * 32 + lane]
                                        : make_float4(0.f, 0.f, 0.f, 0.f);
        }
        #pragma unroll
        for (int j = 0; j < 4; ++j) {
            if (n0 + j < end) {
                float e = cur[j].x * q4.x + cur[j].y * q4.y +
                          cur[j].z * q4.z + cur[j].w * q4.w;
                e += __shfl_xor_sync(0xffffffffu, e, 16);
                e += __shfl_xor_sync(0xffffffffu, e, 8);
                e += __shfl_xor_sync(0xffffffffu, e, 4);
                e += __shfl_xor_sync(0xffffffffu, e, 2);
                e += __shfl_xor_sync(0xffffffffu, e, 1);
                if (e > m) {  // warp-uniform branch
                    float sc = __expf(m - e);
                    s *= sc;
                    racc.x *= sc; racc.y *= sc; racc.z *= sc; racc.w *= sc;
                    m = e;
                }
                float p = __expf(e - m);
                s += p;
                racc.x += p * cur[j].x; racc.y += p * cur[j].y;
                racc.z += p * cur[j].z; racc.w += p * cur[j].w;
            }
        }
        #pragma unroll
        for (int j = 0; j < 4; ++j) cur[j] = nxt[j];
    }

    if (lane == 0) { s_m[wid] = m; s_s[wid] = s; }
    ((float4*)s_r[wid])[lane] = racc;
    __syncthreads();

    // combine 8 per-warp partials -> per-chunk partial
    if (tid < 128) {
        float M = -3.4e38f;
        #pragma unroll
        for (int w = 0; w < 8; ++w)
            if (s_s[w] > 0.f && s_m[w] > M) M = s_m[w];
        float S = 0.f, rs = 0.f;
        #pragma unroll
        for (int w = 0; w < 8; ++w) {
            if (s_s[w] > 0.f) {
                float sc = __expf(s_m[w] - M);
                S  += s_s[w] * sc;
                rs += s_r[w][tid] * sc;
            }
        }
        g_pr[b * DD + tid] = rs;
        if (tid == 0) { g_pm[b] = M; g_ps[b] = S; }
    }
}

// ---------------- combine chunk partials -> r (and final output) -------------
__global__ __launch_bounds__(128) void combine_kernel(float* __restrict__ out,
                                                      int is_last) {
    int g = blockIdx.x, tid = threadIdx.x;
    float M = -3.4e38f;
    #pragma unroll
    for (int w = 0; w < CHUNKS; ++w) {
        float sw = g_ps[g * CHUNKS + w];
        float mw = g_pm[g * CHUNKS + w];
        if (sw > 0.f && mw > M) M = mw;
    }
    float S = 0.f, rs = 0.f;
    #pragma unroll
    for (int w = 0; w < CHUNKS; ++w) {
        float sw = g_ps[g * CHUNKS + w];
        if (sw > 0.f) {
            float sc = __expf(g_pm[g * CHUNKS + w] - M);
            S  += sw * sc;
            rs += g_pr[(g * CHUNKS + w) * DD + tid] * sc;
        }
    }
    float rf = (S > 0.f) ? rs / (S + 1e-16f) : 0.f;
    g_r[g * DD + tid] = rf;
    if (is_last) {
        out[g * 2 * DD + tid]      = g_h[g * DD + tid];  // q
        out[g * 2 * DD + DD + tid] = rf;                 // r
    }
}

// ---------------- launch ----------------
extern "C" void kernel_launch(void* const* d_in, const int* in_sizes, int n_in,
                              void* d_out, int out_size) {
    const float* x    = (const float*)d_in[0];
    const void*  bi   = d_in[1];
    const float* W_ih = (const float*)d_in[2];
    const float* W_hh = (const float*)d_in[3];
    const float* b_ih = (const float*)d_in[4];
    const float* b_hh = (const float*)d_in[5];
    float* out = (float*)d_out;

    detect_kernel<<<1, 1>>>((const int*)bi);
    prep_kernel<<<512, 256>>>(W_ih, W_hh, b_ih, b_hh);
    init_kernel<<<512, 256>>>();
    offsets_kernel<<<(NN + 255) / 256, 256>>>(bi);

    for (int step = 0; step < STEPS; ++step) {
        lstm_kernel<<<dim3(64, 2), 256>>>();
        lstm_act_kernel<<<BB, 128>>>();
        attn_kernel<<<NPART, 256>>>(x);
        combine_kernel<<<BB, 128>>>(out, step == STEPS - 1 ? 1 : 0);
    }
}

// round 3
// speedup vs baseline: 1.1999x; 1.1367x over previous
#include <cuda_runtime.h>

#define NN 2000000
#define DD 128
#define BB 1024
#define STEPS 3
#define CHUNKS 16                // chunks per graph
#define NPART (BB * CHUNKS)      // 16384 partial slots

// ---------------- device scratch (no allocs allowed) ----------------
__device__ int   g_is64;
__device__ int   g_off[BB + 1];
__device__ float g_h[BB * DD];
__device__ float g_c[BB * DD];
__device__ float g_Weff[4 * DD * 2 * DD];  // 512 x 256
__device__ float g_bias[4 * DD];
__device__ float g_pm[NPART];              // per-chunk running max
__device__ float g_ps[NPART];              // per-chunk exp-sum
__device__ float g_pr[NPART * DD];         // per-chunk pooled partial (8 MB)

__device__ __forceinline__ float sigf(float v) { return 1.f / (1.f + __expf(-v)); }

// ---------------- setup: weight fold + bias fold + dtype detect ----------------
// gates = [h_prev, r_prev] @ Weff^T + (b_ih + b_hh)
// Weff[:,0:128] = W_ih[:,0:128] + W_hh ; Weff[:,128:256] = W_ih[:,128:256]
// int64 detect: sorted values < 2^31 => odd int32 words are all zero.
__global__ void setup_kernel(const float* __restrict__ W_ih, const float* __restrict__ W_hh,
                             const float* __restrict__ b_ih, const float* __restrict__ b_hh,
                             const int* __restrict__ bi32) {
    int id = blockIdx.x * blockDim.x + threadIdx.x;  // 131072 threads
    int gg = id >> 8, k = id & 255;
    float w = W_ih[gg * 256 + k];
    if (k < 128) w += W_hh[gg * 128 + k];
    g_Weff[id] = w;
    if (id < 4 * DD) g_bias[id] = b_ih[id] + b_hh[id];
    if (id == 0)
        g_is64 = (bi32[NN - 1] == 0 && bi32[(NN / 2) | 1] == 0 &&
                  bi32[(NN / 4) | 1] == 0) ? 1 : 0;
}

__device__ __forceinline__ int load_bi(const void* bi, int i, int is64) {
    if (is64) return (int)((const long long*)bi)[i];
    return ((const int*)bi)[i];
}

// ---------------- graph start offsets (batch_index sorted), 8 elems/thread ----
__global__ void offsets_kernel(const void* __restrict__ bi) {
    int t = blockIdx.x * blockDim.x + threadIdx.x;
    if (t >= NN / 8) return;
    int i0 = t * 8;
    int is64 = g_is64;
    int v[8];
    if (is64) {
        const longlong2* p = (const longlong2*)bi + t * 4;
        longlong2 a = p[0], b = p[1], c = p[2], d = p[3];
        v[0] = (int)a.x; v[1] = (int)a.y; v[2] = (int)b.x; v[3] = (int)b.y;
        v[4] = (int)c.x; v[5] = (int)c.y; v[6] = (int)d.x; v[7] = (int)d.y;
    } else {
        const int4* p = (const int4*)bi + t * 2;
        int4 a = p[0], b = p[1];
        v[0] = a.x; v[1] = a.y; v[2] = a.z; v[3] = a.w;
        v[4] = b.x; v[5] = b.y; v[6] = b.z; v[7] = b.w;
    }
    int prev = (i0 == 0) ? -1 : load_bi(bi, i0 - 1, is64);
    #pragma unroll
    for (int j = 0; j < 8; ++j) {
        for (int g = prev + 1; g <= v[j]; ++g) g_off[g] = i0 + j;
        prev = v[j];
    }
    if (i0 + 8 == NN)
        for (int g = prev + 1; g <= BB; ++g) g_off[g] = NN;
}

// ---------------- step 0 LSTM: q*=0, h=0 => gates = bias ----------------
__global__ void act0_kernel() {
    int id = blockIdx.x * blockDim.x + threadIdx.x;  // BB*128
    int c = id & 127;
    float gi = g_bias[c];
    float gg = g_bias[c + 256];
    float go = g_bias[c + 384];
    float cn = sigf(gi) * tanhf(gg);        // sig(f)*c0 term is 0
    float hn = sigf(go) * tanhf(cn);
    g_c[id] = cn;
    g_h[id] = hn;
}

// ---------------- chunked online-softmax attention pooling (partials) --------
// Block b handles chunk (b & 15) of graph (b >> 4). One streaming pass.
__global__ __launch_bounds__(256) void attn_kernel(const float* __restrict__ x) {
    __shared__ float s_q[128];
    __shared__ float s_r[8][128];
    __shared__ float s_m[8];
    __shared__ float s_s[8];

    int b = blockIdx.x;
    int g = b >> 4, cidx = b & 15;
    int tid = threadIdx.x;

    if (tid < 128) s_q[tid] = g_h[g * DD + tid];
    __syncthreads();

    int gs = g_off[g], ge = g_off[g + 1], len = ge - gs;
    int start = gs + (len * cidx) / CHUNKS;
    int end   = gs + (len * (cidx + 1)) / CHUNKS;

    int lane = tid & 31, wid = tid >> 5;
    float4 q4 = ((const float4*)s_q)[lane];
    const float4* x4 = (const float4*)x;

    float m = -3.4e38f;
    float s = 0.f;
    float4 racc = make_float4(0.f, 0.f, 0.f, 0.f);

    // 8 warps x 4-node unroll, double-buffered prefetch, streaming loads
    int n0 = start + wid * 4;
    float4 cur[4];
    if (n0 < end) {
        #pragma unroll
        for (int j = 0; j < 4; ++j)
            cur[j] = (n0 + j < end) ? __ldcs(&x4[(n0 + j) * 32 + lane])
                                    : make_float4(0.f, 0.f, 0.f, 0.f);
    }
    for (; n0 < end; n0 += 32) {
        int n1 = n0 + 32;
        float4 nxt[4];
        if (n1 < end) {
            #pragma unroll
            for (int j = 0; j < 4; ++j)
                nxt[j] = (n1 + j < end) ? __ldcs(&x4[(n1 + j) * 32 + lane])
                                        : make_float4(0.f, 0.f, 0.f, 0.f);
        }
        float e[4];
        #pragma unroll
        for (int j = 0; j < 4; ++j) {
            float d = cur[j].x * q4.x + cur[j].y * q4.y +
                      cur[j].z * q4.z + cur[j].w * q4.w;
            d += __shfl_xor_sync(0xffffffffu, d, 16);
            d += __shfl_xor_sync(0xffffffffu, d, 8);
            d += __shfl_xor_sync(0xffffffffu, d, 4);
            d += __shfl_xor_sync(0xffffffffu, d, 2);
            d += __shfl_xor_sync(0xffffffffu, d, 1);
            e[j] = (n0 + j < end) ? d : -3.4e38f;  // padded tail -> p = 0
        }
        float em = fmaxf(fmaxf(e[0], e[1]), fmaxf(e[2], e[3]));
        if (em > m) {  // rare, warp-uniform; amortized over 4 nodes
            float sc = __expf(m - em);
            s *= sc;
            racc.x *= sc; racc.y *= sc; racc.z *= sc; racc.w *= sc;
            m = em;
        }
        #pragma unroll
        for (int j = 0; j < 4; ++j) {
            float p = __expf(e[j] - m);
            s += p;
            racc.x += p * cur[j].x; racc.y += p * cur[j].y;
            racc.z += p * cur[j].z; racc.w += p * cur[j].w;
        }
        #pragma unroll
        for (int j = 0; j < 4; ++j) cur[j] = nxt[j];
    }

    if (lane == 0) { s_m[wid] = m; s_s[wid] = s; }
    ((float4*)s_r[wid])[lane] = racc;
    __syncthreads();

    // combine 8 per-warp partials -> per-chunk partial
    if (tid < 128) {
        float M = -3.4e38f;
        #pragma unroll
        for (int w = 0; w < 8; ++w)
            if (s_s[w] > 0.f && s_m[w] > M) M = s_m[w];
        float S = 0.f, rs = 0.f;
        #pragma unroll
        for (int w = 0; w < 8; ++w) {
            if (s_s[w] > 0.f) {
                float sc = __expf(s_m[w] - M);
                S  += s_s[w] * sc;
                rs += s_r[w][tid] * sc;
            }
        }
        g_pr[b * DD + tid] = rs;
        if (tid == 0) { g_pm[b] = M; g_ps[b] = S; }
    }
}

// ---------------- fused: combine partials -> r, GEMM, activation -------------
// Block handles 8 graphs. s_in = [h, r] built in smem; gates in smem; h,c out.
__global__ __launch_bounds__(256) void lstm_kernel() {
    __shared__ float s_in[8][256];     // [h | r]
    __shared__ float s_gate[8][512];
    __shared__ float s_scale[8][CHUNKS];
    __shared__ float s_S[8];

    int g0 = blockIdx.x * 8;
    int tid = threadIdx.x;

    // A: per-graph softmax-combine scales (8 threads)
    if (tid < 8) {
        int g = g0 + tid;
        float M = -3.4e38f;
        #pragma unroll
        for (int w = 0; w < CHUNKS; ++w) {
            float sw = g_ps[g * CHUNKS + w], mw = g_pm[g * CHUNKS + w];
            if (sw > 0.f && mw > M) M = mw;
        }
        float S = 0.f;
        #pragma unroll
        for (int w = 0; w < CHUNKS; ++w) {
            float sw = g_ps[g * CHUNKS + w];
            float sc = (sw > 0.f) ? __expf(g_pm[g * CHUNKS + w] - M) : 0.f;
            s_scale[tid][w] = sc;
            S += sw * sc;
        }
        s_S[tid] = S;
    }
    // B: h into s_in[:, 0:128]
    for (int it = tid; it < 8 * 128; it += 256) {
        int g = it >> 7, c = it & 127;
        s_in[g][c] = g_h[(g0 + g) * DD + c];
    }
    __syncthreads();
    // C: r into s_in[:, 128:256]
    for (int it = tid; it < 8 * 128; it += 256) {
        int g = it >> 7, c = it & 127;
        float rs = 0.f;
        #pragma unroll
        for (int w = 0; w < CHUNKS; ++w)
            rs += s_scale[g][w] * g_pr[((g0 + g) * CHUNKS + w) * DD + c];
        float S = s_S[g];
        s_in[g][128 + c] = (S > 0.f) ? rs / (S + 1e-16f) : 0.f;
    }
    __syncthreads();
    // D: GEMM: this thread owns gate cols tid and tid+256 for all 8 rows
    float acc0[8], acc1[8];
    #pragma unroll
    for (int t = 0; t < 8; ++t) { acc0[t] = 0.f; acc1[t] = 0.f; }
    const float4* w0 = (const float4*)(g_Weff + tid * 256);
    const float4* w1 = (const float4*)(g_Weff + (tid + 256) * 256);
    #pragma unroll 4
    for (int k4 = 0; k4 < 64; ++k4) {
        float4 wa = w0[k4], wb = w1[k4];
        #pragma unroll
        for (int t = 0; t < 8; ++t) {
            float4 iv = *(const float4*)&s_in[t][k4 * 4];
            acc0[t] += wa.x * iv.x + wa.y * iv.y + wa.z * iv.z + wa.w * iv.w;
            acc1[t] += wb.x * iv.x + wb.y * iv.y + wb.z * iv.z + wb.w * iv.w;
        }
    }
    float b0 = g_bias[tid], b1 = g_bias[tid + 256];
    #pragma unroll
    for (int t = 0; t < 8; ++t) {
        s_gate[t][tid]       = acc0[t] + b0;
        s_gate[t][tid + 256] = acc1[t] + b1;
    }
    __syncthreads();
    // E: LSTM activation -> h, c
    for (int it = tid; it < 8 * 128; it += 256) {
        int g = it >> 7, c = it & 127;
        float gi = s_gate[g][c];
        float gf = s_gate[g][c + 128];
        float gg = s_gate[g][c + 256];
        float go = s_gate[g][c + 384];
        int idx = (g0 + g) * DD + c;
        float cn = sigf(gf) * g_c[idx] + sigf(gi) * tanhf(gg);
        float hn = sigf(go) * tanhf(cn);
        g_c[idx] = cn;
        g_h[idx] = hn;
    }
}

// ---------------- final combine: r from partials, write [q, r] ---------------
__global__ __launch_bounds__(128) void combine_out_kernel(float* __restrict__ out) {
    int g = blockIdx.x, tid = threadIdx.x;
    float M = -3.4e38f;
    #pragma unroll
    for (int w = 0; w < CHUNKS; ++w) {
        float sw = g_ps[g * CHUNKS + w], mw = g_pm[g * CHUNKS + w];
        if (sw > 0.f && mw > M) M = mw;
    }
    float S = 0.f, rs = 0.f;
    #pragma unroll
    for (int w = 0; w < CHUNKS; ++w) {
        float sw = g_ps[g * CHUNKS + w];
        if (sw > 0.f) {
            float sc = __expf(g_pm[g * CHUNKS + w] - M);
            S  += sw * sc;
            rs += g_pr[(g * CHUNKS + w) * DD + tid] * sc;
        }
    }
    float rf = (S > 0.f) ? rs / (S + 1e-16f) : 0.f;
    out[g * 2 * DD + tid]      = g_h[g * DD + tid];  // q
    out[g * 2 * DD + DD + tid] = rf;                 // r
}

// ---------------- launch (9 kernels) ----------------
extern "C" void kernel_launch(void* const* d_in, const int* in_sizes, int n_in,
                              void* d_out, int out_size) {
    const float* x    = (const float*)d_in[0];
    const void*  bi   = d_in[1];
    const float* W_ih = (const float*)d_in[2];
    const float* W_hh = (const float*)d_in[3];
    const float* b_ih = (const float*)d_in[4];
    const float* b_hh = (const float*)d_in[5];
    float* out = (float*)d_out;

    setup_kernel<<<512, 256>>>(W_ih, W_hh, b_ih, b_hh, (const int*)bi);
    offsets_kernel<<<(NN / 8 + 255) / 256, 256>>>(bi);
    act0_kernel<<<512, 256>>>();
    attn_kernel<<<NPART, 256>>>(x);
    lstm_kernel<<<BB / 8, 256>>>();
    attn_kernel<<<NPART, 256>>>(x);
    lstm_kernel<<<BB / 8, 256>>>();
    attn_kernel<<<NPART, 256>>>(x);
    combine_out_kernel<<<BB, 128>>>(out);
}

// round 5
// speedup vs baseline: 1.2535x; 1.0447x over previous
#include <cuda_runtime.h>
#include <cstdint>

#define NN 2000000
#define DD 128
#define BB 1024
#define STEPS 3
#define CHUNKS 16                // chunks per graph
#define NPART (BB * CHUNKS)      // 16384 partial slots
#define TILE 24                  // nodes per pipeline stage
#define NSTAGE 3

// ---------------- device scratch (no allocs allowed) ----------------
__device__ int   g_is64;
__device__ int   g_off[BB + 1];
__device__ float g_h[BB * DD];
__device__ float g_c[BB * DD];
__device__ float g_Weff[4 * DD * 2 * DD];  // 512 x 256
__device__ float g_bias[4 * DD];
__device__ float g_pm[NPART];              // per-chunk running max
__device__ float g_ps[NPART];              // per-chunk exp-sum
__device__ float g_pr[NPART * DD];         // per-chunk pooled partial (8 MB)

__device__ __forceinline__ float sigf(float v) { return 1.f / (1.f + __expf(-v)); }

__device__ __forceinline__ void cp_async16(unsigned int dst, const void* src) {
    asm volatile("cp.async.cg.shared.global [%0], [%1], 16;" :: "r"(dst), "l"(src));
}

// ---------------- setup: weight fold + bias fold + dtype detect ----------------
// gates = [h_prev, r_prev] @ Weff^T + (b_ih + b_hh)
// Weff[:,0:128] = W_ih[:,0:128] + W_hh ; Weff[:,128:256] = W_ih[:,128:256]
// int64 detect: sorted values < 2^31 => odd int32 words all zero.
__global__ void setup_kernel(const float* __restrict__ W_ih, const float* __restrict__ W_hh,
                             const float* __restrict__ b_ih, const float* __restrict__ b_hh,
                             const int* __restrict__ bi32) {
    int id = blockIdx.x * blockDim.x + threadIdx.x;  // 131072 threads
    int gg = id >> 8, k = id & 255;
    float w = W_ih[gg * 256 + k];
    if (k < 128) w += W_hh[gg * 128 + k];
    g_Weff[id] = w;
    if (id < 4 * DD) g_bias[id] = b_ih[id] + b_hh[id];
    if (id == 0)
        g_is64 = (bi32[NN - 1] == 0 && bi32[(NN / 2) | 1] == 0 &&
                  bi32[(NN / 4) | 1] == 0) ? 1 : 0;
}

__device__ __forceinline__ int load_bi(const void* bi, int i, int is64) {
    if (is64) return (int)((const long long*)bi)[i];
    return ((const int*)bi)[i];
}

// ---------------- graph start offsets (batch_index sorted), 8 elems/thread ----
__global__ void offsets_kernel(const void* __restrict__ bi) {
    int t = blockIdx.x * blockDim.x + threadIdx.x;
    if (t >= NN / 8) return;
    int i0 = t * 8;
    int is64 = g_is64;
    int v[8];
    if (is64) {
        const longlong2* p = (const longlong2*)bi + t * 4;
        longlong2 a = p[0], b = p[1], c = p[2], d = p[3];
        v[0] = (int)a.x; v[1] = (int)a.y; v[2] = (int)b.x; v[3] = (int)b.y;
        v[4] = (int)c.x; v[5] = (int)c.y; v[6] = (int)d.x; v[7] = (int)d.y;
    } else {
        const int4* p = (const int4*)bi + t * 2;
        int4 a = p[0], b = p[1];
        v[0] = a.x; v[1] = a.y; v[2] = a.z; v[3] = a.w;
        v[4] = b.x; v[5] = b.y; v[6] = b.z; v[7] = b.w;
    }
    int prev = (i0 == 0) ? -1 : load_bi(bi, i0 - 1, is64);
    #pragma unroll
    for (int j = 0; j < 8; ++j) {
        for (int g = prev + 1; g <= v[j]; ++g) g_off[g] = i0 + j;
        prev = v[j];
    }
    if (i0 + 8 == NN)
        for (int g = prev + 1; g <= BB; ++g) g_off[g] = NN;
}

// ---------------- step 0 LSTM: q*=0, h=0 => gates = bias ----------------
__global__ void act0_kernel() {
    int id = blockIdx.x * blockDim.x + threadIdx.x;  // BB*128
    int c = id & 127;
    float gi = g_bias[c];
    float gg = g_bias[c + 256];
    float go = g_bias[c + 384];
    float cn = sigf(gi) * tanhf(gg);        // sig(f)*c0 term is 0
    float hn = sigf(go) * tanhf(cn);
    g_c[id] = cn;
    g_h[id] = hn;
}

// ---------------- chunked online-softmax attention pooling (partials) --------
// Block b handles chunk (b & 15) of graph (b >> 4). cp.async 3-stage pipeline:
// loads decoupled from registers; tiles of 24 nodes staged in smem.
__global__ __launch_bounds__(256) void attn_kernel(const float* __restrict__ x) {
    __shared__ float4 s_tile[NSTAGE][TILE * 32];   // 3 x 12KB
    __shared__ float  s_q[128];
    __shared__ float  s_r[8][128];
    __shared__ float  s_m[8];
    __shared__ float  s_s[8];

    int b = blockIdx.x;
    int g = b >> 4, cidx = b & 15;
    int tid = threadIdx.x;
    int lane = tid & 31, wid = tid >> 5;

    if (tid < 128) s_q[tid] = g_h[g * DD + tid];

    int gs = g_off[g], ge = g_off[g + 1], len = ge - gs;
    int start = gs + (len * cidx) / CHUNKS;
    int end   = gs + (len * (cidx + 1)) / CHUNKS;
    int nt = (end > start) ? (end - start + TILE - 1) / TILE : 0;

    unsigned int s_base = (unsigned int)__cvta_generic_to_shared(s_tile);
    const float4* x4 = (const float4*)x;

    // issue tile t into buffer t % NSTAGE (clamped tail); always commit a group
    auto issue_tile = [&](int t) {
        if (t < nt) {
            int base = start + t * TILE;
            unsigned int dst0 = s_base + (unsigned int)((t % NSTAGE) * (TILE * 32) << 4);
            #pragma unroll
            for (int k = 0; k < 3; ++k) {
                int c = tid + 256 * k;            // 0..767 (16B chunk index)
                int node = base + (c >> 5);
                if (node >= end) node = end - 1;  // tail clamp: L2-hit duplicate
                cp_async16(dst0 + ((unsigned int)c << 4),
                           x4 + (size_t)node * 32 + (c & 31));
            }
        }
        asm volatile("cp.async.commit_group;" ::: "memory");
    };

    issue_tile(0);
    issue_tile(1);

    float m = -3.4e38f;
    float s = 0.f;
    float4 racc = make_float4(0.f, 0.f, 0.f, 0.f);
    float4 q4;

    __syncthreads();              // s_q visible (also covers nt==0 path)
    q4 = ((const float4*)s_q)[lane];

    for (int t = 0; t < nt; ++t) {
        asm volatile("cp.async.wait_group 1;" ::: "memory");  // tile t ready
        __syncthreads();          // all warps done with tile t-1's buffer reuse
        issue_tile(t + 2);        // writes buffer (t+2)%3 (last used by t-1)

        const float4* tile = s_tile[t % NSTAGE];
        int nbase = start + t * TILE;
        float4 xv[3];
        float e[3];
        #pragma unroll
        for (int j = 0; j < 3; ++j) {
            int nl = wid * 3 + j;                 // 0..23
            xv[j] = tile[(nl << 5) + lane];
            float d = xv[j].x * q4.x + xv[j].y * q4.y +
                      xv[j].z * q4.z + xv[j].w * q4.w;
            d += __shfl_xor_sync(0xffffffffu, d, 16);
            d += __shfl_xor_sync(0xffffffffu, d, 8);
            d += __shfl_xor_sync(0xffffffffu, d, 4);
            d += __shfl_xor_sync(0xffffffffu, d, 2);
            d += __shfl_xor_sync(0xffffffffu, d, 1);
            e[j] = (nbase + nl < end) ? d : -3.4e38f;  // padded -> p = 0
        }
        float em = fmaxf(fmaxf(e[0], e[1]), e[2]);
        if (em > m) {             // rare, warp-uniform
            float sc = __expf(m - em);
            s *= sc;
            racc.x *= sc; racc.y *= sc; racc.z *= sc; racc.w *= sc;
            m = em;
        }
        #pragma unroll
        for (int j = 0; j < 3; ++j) {
            float p = __expf(e[j] - m);
            s += p;
            racc.x += p * xv[j].x; racc.y += p * xv[j].y;
            racc.z += p * xv[j].z; racc.w += p * xv[j].w;
        }
    }

    if (lane == 0) { s_m[wid] = m; s_s[wid] = s; }
    ((float4*)s_r[wid])[lane] = racc;
    __syncthreads();

    // combine 8 per-warp partials -> per-chunk partial
    if (tid < 128) {
        float M = -3.4e38f;
        #pragma unroll
        for (int w = 0; w < 8; ++w)
            if (s_s[w] > 0.f && s_m[w] > M) M = s_m[w];
        float S = 0.f, rs = 0.f;
        #pragma unroll
        for (int w = 0; w < 8; ++w) {
            if (s_s[w] > 0.f) {
                float sc = __expf(s_m[w] - M);
                S  += s_s[w] * sc;
                rs += s_r[w][tid] * sc;
            }
        }
        g_pr[b * DD + tid] = rs;
        if (tid == 0) { g_pm[b] = M; g_ps[b] = S; }
    }
}

// ---------------- fused: combine partials -> r, GEMM, activation -------------
__global__ __launch_bounds__(256) void lstm_kernel() {
    __shared__ float s_in[8][256];     // [h | r]
    __shared__ float s_gate[8][512];
    __shared__ float s_scale[8][CHUNKS];
    __shared__ float s_S[8];

    int g0 = blockIdx.x * 8;
    int tid = threadIdx.x;

    if (tid < 8) {
        int g = g0 + tid;
        float M = -3.4e38f;
        #pragma unroll
        for (int w = 0; w < CHUNKS; ++w) {
            float sw = g_ps[g * CHUNKS + w], mw = g_pm[g * CHUNKS + w];
            if (sw > 0.f && mw > M) M = mw;
        }
        float S = 0.f;
        #pragma unroll
        for (int w = 0; w < CHUNKS; ++w) {
            float sw = g_ps[g * CHUNKS + w];
            float sc = (sw > 0.f) ? __expf(g_pm[g * CHUNKS + w] - M) : 0.f;
            s_scale[tid][w] = sc;
            S += sw * sc;
        }
        s_S[tid] = S;
    }
    for (int it = tid; it < 8 * 128; it += 256) {
        int g = it >> 7, c = it & 127;
        s_in[g][c] = g_h[(g0 + g) * DD + c];
    }
    __syncthreads();
    for (int it = tid; it < 8 * 128; it += 256) {
        int g = it >> 7, c = it & 127;
        float rs = 0.f;
        #pragma unroll
        for (int w = 0; w < CHUNKS; ++w)
            rs += s_scale[g][w] * g_pr[((g0 + g) * CHUNKS + w) * DD + c];
        float S = s_S[g];
        s_in[g][128 + c] = (S > 0.f) ? rs / (S + 1e-16f) : 0.f;
    }
    __syncthreads();
    float acc0[8], acc1[8];
    #pragma unroll
    for (int t = 0; t < 8; ++t) { acc0[t] = 0.f; acc1[t] = 0.f; }
    const float4* w0 = (const float4*)(g_Weff + tid * 256);
    const float4* w1 = (const float4*)(g_Weff + (tid + 256) * 256);
    #pragma unroll 4
    for (int k4 = 0; k4 < 64; ++k4) {
        float4 wa = w0[k4], wb = w1[k4];
        #pragma unroll
        for (int t = 0; t < 8; ++t) {
            float4 iv = *(const float4*)&s_in[t][k4 * 4];
            acc0[t] += wa.x * iv.x + wa.y * iv.y + wa.z * iv.z + wa.w * iv.w;
            acc1[t] += wb.x * iv.x + wb.y * iv.y + wb.z * iv.z + wb.w * iv.w;
        }
    }
    float b0 = g_bias[tid], b1 = g_bias[tid + 256];
    #pragma unroll
    for (int t = 0; t < 8; ++t) {
        s_gate[t][tid]       = acc0[t] + b0;
        s_gate[t][tid + 256] = acc1[t] + b1;
    }
    __syncthreads();
    for (int it = tid; it < 8 * 128; it += 256) {
        int g = it >> 7, c = it & 127;
        float gi = s_gate[g][c];
        float gf = s_gate[g][c + 128];
        float gg = s_gate[g][c + 256];
        float go = s_gate[g][c + 384];
        int idx = (g0 + g) * DD + c;
        float cn = sigf(gf) * g_c[idx] + sigf(gi) * tanhf(gg);
        float hn = sigf(go) * tanhf(cn);
        g_c[idx] = cn;
        g_h[idx] = hn;
    }
}

// ---------------- final combine: r from partials, write [q, r] ---------------
__global__ __launch_bounds__(128) void combine_out_kernel(float* __restrict__ out) {
    int g = blockIdx.x, tid = threadIdx.x;
    float M = -3.4e38f;
    #pragma unroll
    for (int w = 0; w < CHUNKS; ++w) {
        float sw = g_ps[g * CHUNKS + w], mw = g_pm[g * CHUNKS + w];
        if (sw > 0.f && mw > M) M = mw;
    }
    float S = 0.f, rs = 0.f;
    #pragma unroll
    for (int w = 0; w < CHUNKS; ++w) {
        float sw = g_ps[g * CHUNKS + w];
        if (sw > 0.f) {
            float sc = __expf(g_pm[g * CHUNKS + w] - M);
            S  += sw * sc;
            rs += g_pr[(g * CHUNKS + w) * DD + tid] * sc;
        }
    }
    float rf = (S > 0.f) ? rs / (S + 1e-16f) : 0.f;
    out[g * 2 * DD + tid]      = g_h[g * DD + tid];  // q
    out[g * 2 * DD + DD + tid] = rf;                 // r
}

// ---------------- launch (9 kernels) ----------------
extern "C" void kernel_launch(void* const* d_in, const int* in_sizes, int n_in,
                              void* d_out, int out_size) {
    const float* x    = (const float*)d_in[0];
    const void*  bi   = d_in[1];
    const float* W_ih = (const float*)d_in[2];
    const float* W_hh = (const float*)d_in[3];
    const float* b_ih = (const float*)d_in[4];
    const float* b_hh = (const float*)d_in[5];
    float* out = (float*)d_out;

    setup_kernel<<<512, 256>>>(W_ih, W_hh, b_ih, b_hh, (const int*)bi);
    offsets_kernel<<<(NN / 8 + 255) / 256, 256>>>(bi);
    act0_kernel<<<512, 256>>>();
    attn_kernel<<<NPART, 256>>>(x);
    lstm_kernel<<<BB / 8, 256>>>();
    attn_kernel<<<NPART, 256>>>(x);
    lstm_kernel<<<BB / 8, 256>>>();
    attn_kernel<<<NPART, 256>>>(x);
    combine_out_kernel<<<BB, 128>>>(out);
}

// round 8
// speedup vs baseline: 1.2815x; 1.0223x over previous
#include <cuda_runtime.h>
#include <cstdint>

#define NN 2000000
#define DD 128
#define BB 1024
#define STEPS 3
#define CHUNKS 16                // chunks per graph
#define NPART (BB * CHUNKS)      // 16384 partial slots
#define TILE 16                  // nodes per pipeline stage
#define NSTAGE 4

// ---------------- device scratch (no allocs allowed) ----------------
__device__ int   g_is64;
__device__ int   g_off[BB + 1];
__device__ float g_h[BB * DD];
__device__ float g_c[BB * DD];
__device__ float g_Weff[4 * DD * 2 * DD];  // 512 x 256
__device__ float g_bias[4 * DD];
__device__ float g_pm[NPART];              // per-chunk running max
__device__ float g_ps[NPART];              // per-chunk exp-sum
__device__ float g_pr[NPART * DD];         // per-chunk pooled partial (8 MB)

__device__ __forceinline__ float sigf(float v) { return 1.f / (1.f + __expf(-v)); }

__device__ __forceinline__ void cp_async16(unsigned int dst, const void* src) {
    asm volatile("cp.async.cg.shared.global [%0], [%1], 16;" :: "r"(dst), "l"(src));
}

__device__ __forceinline__ float warp_sum(float d) {
    d += __shfl_xor_sync(0xffffffffu, d, 16);
    d += __shfl_xor_sync(0xffffffffu, d, 8);
    d += __shfl_xor_sync(0xffffffffu, d, 4);
    d += __shfl_xor_sync(0xffffffffu, d, 2);
    d += __shfl_xor_sync(0xffffffffu, d, 1);
    return d;
}

// ---------------- setup: weight fold + bias fold + dtype detect + step0 LSTM --
// gates = [h_prev, r_prev] @ Weff^T + (b_ih + b_hh)
// Weff[:,0:128] = W_ih[:,0:128] + W_hh ; Weff[:,128:256] = W_ih[:,128:256]
// Step 0: q*=0, h=0, c=0 => gates = bias => h0,c0 closed form (per-thread).
// int64 detect: sorted values < 2^31 => odd int32 words all zero.
__global__ void setup_kernel(const float* __restrict__ W_ih, const float* __restrict__ W_hh,
                             const float* __restrict__ b_ih, const float* __restrict__ b_hh,
                             const int* __restrict__ bi32) {
    int id = blockIdx.x * blockDim.x + threadIdx.x;  // 131072 threads == BB*128
    int gg = id >> 8, k = id & 255;
    float w = W_ih[gg * 256 + k];
    if (k < 128) w += W_hh[gg * 128 + k];
    g_Weff[id] = w;
    if (id < 4 * DD) g_bias[id] = b_ih[id] + b_hh[id];

    // step-0 LSTM state (one thread per (graph, channel))
    int c = id & 127;
    float gi = b_ih[c]       + b_hh[c];
    float gG = b_ih[c + 256] + b_hh[c + 256];
    float go = b_ih[c + 384] + b_hh[c + 384];
    float cn = sigf(gi) * tanhf(gG);        // sig(f)*c0 term is 0
    float hn = sigf(go) * tanhf(cn);
    g_c[id] = cn;
    g_h[id] = hn;

    if (id == 0)
        g_is64 = (bi32[NN - 1] == 0 && bi32[(NN / 2) | 1] == 0 &&
                  bi32[(NN / 4) | 1] == 0) ? 1 : 0;
}

__device__ __forceinline__ int load_bi(const void* bi, int i, int is64) {
    if (is64) return (int)((const long long*)bi)[i];
    return ((const int*)bi)[i];
}

// ---------------- graph start offsets (batch_index sorted), 8 elems/thread ----
__global__ void offsets_kernel(const void* __restrict__ bi) {
    int t = blockIdx.x * blockDim.x + threadIdx.x;
    if (t >= NN / 8) return;
    int i0 = t * 8;
    int is64 = g_is64;
    int v[8];
    if (is64) {
        const longlong2* p = (const longlong2*)bi + t * 4;
        longlong2 a = p[0], b = p[1], c = p[2], d = p[3];
        v[0] = (int)a.x; v[1] = (int)a.y; v[2] = (int)b.x; v[3] = (int)b.y;
        v[4] = (int)c.x; v[5] = (int)c.y; v[6] = (int)d.x; v[7] = (int)d.y;
    } else {
        const int4* p = (const int4*)bi + t * 2;
        int4 a = p[0], b = p[1];
        v[0] = a.x; v[1] = a.y; v[2] = a.z; v[3] = a.w;
        v[4] = b.x; v[5] = b.y; v[6] = b.z; v[7] = b.w;
    }
    int prev = (i0 == 0) ? -1 : load_bi(bi, i0 - 1, is64);
    #pragma unroll
    for (int j = 0; j < 8; ++j) {
        for (int g = prev + 1; g <= v[j]; ++g) g_off[g] = i0 + j;
        prev = v[j];
    }
    if (i0 + 8 == NN)
        for (int g = prev + 1; g <= BB; ++g) g_off[g] = NN;
}

// ---------------- chunked online-softmax attention pooling (partials) --------
// Block b handles chunk (b & 15) of graph (b >> 4). 4-stage cp.async pipeline,
// 3 tiles in flight; 6 blocks/SM.
__global__ __launch_bounds__(256, 6) void attn_kernel(const float* __restrict__ x) {
    __shared__ float4 s_tile[NSTAGE][TILE * 32];   // 4 x 8KB
    __shared__ float  s_q[128];
    __shared__ float  s_r[8][128];
    __shared__ float  s_m[8];
    __shared__ float  s_s[8];

    int b = blockIdx.x;
    int g = b >> 4, cidx = b & 15;
    int tid = threadIdx.x;
    int lane = tid & 31, wid = tid >> 5;

    if (tid < 128) s_q[tid] = g_h[g * DD + tid];

    int gs = g_off[g], ge = g_off[g + 1], len = ge - gs;
    int start = gs + (len * cidx) / CHUNKS;
    int end   = gs + (len * (cidx + 1)) / CHUNKS;
    int nt = (end > start) ? (end - start + TILE - 1) / TILE : 0;

    unsigned int s_base = (unsigned int)__cvta_generic_to_shared(s_tile);
    const float4* x4 = (const float4*)x;

    // issue tile t into buffer t % NSTAGE (clamped tail); always commit a group
    auto issue_tile = [&](int t) {
        if (t < nt) {
            int base = start + t * TILE;
            unsigned int dst0 = s_base + (unsigned int)((t % NSTAGE) * (TILE * 32) << 4);
            #pragma unroll
            for (int k = 0; k < 2; ++k) {
                int c = tid + 256 * k;            // 0..511 (16B chunk index)
                int node = base + (c >> 5);
                if (node >= end) node = end - 1;  // tail clamp: L2-hit duplicate
                cp_async16(dst0 + ((unsigned int)c << 4),
                           x4 + (size_t)node * 32 + (c & 31));
            }
        }
        asm volatile("cp.async.commit_group;" ::: "memory");
    };

    issue_tile(0);
    issue_tile(1);
    issue_tile(2);

    float m = -3.4e38f;
    float s = 0.f;
    float4 racc = make_float4(0.f, 0.f, 0.f, 0.f);
    float4 q4;

    __syncthreads();              // s_q visible (also covers nt==0 path)
    q4 = ((const float4*)s_q)[lane];

    for (int t = 0; t < nt; ++t) {
        asm volatile("cp.async.wait_group 2;" ::: "memory");  // tile t ready
        __syncthreads();          // all warps done with buf (t-1)%4 == (t+3)%4
        issue_tile(t + 3);        // refill newest stage

        const float4* tile = s_tile[t % NSTAGE];
        int nbase = start + t * TILE;
        float4 xv[2];
        float e[2];
        #pragma unroll
        for (int j = 0; j < 2; ++j) {
            int nl = wid * 2 + j;                 // 0..15
            xv[j] = tile[(nl << 5) + lane];
            float d = xv[j].x * q4.x + xv[j].y * q4.y +
                      xv[j].z * q4.z + xv[j].w * q4.w;
            d = warp_sum(d);
            e[j] = (nbase + nl < end) ? d : -3.4e38f;  // padded -> p = 0
        }
        float em = fmaxf(e[0], e[1]);
        if (em > m) {             // rare, warp-uniform
            float sc = __expf(m - em);
            s *= sc;
            racc.x *= sc; racc.y *= sc; racc.z *= sc; racc.w *= sc;
            m = em;
        }
        #pragma unroll
        for (int j = 0; j < 2; ++j) {
            float p = __expf(e[j] - m);
            s += p;
            racc.x += p * xv[j].x; racc.y += p * xv[j].y;
            racc.z += p * xv[j].z; racc.w += p * xv[j].w;
        }
    }

    if (lane == 0) { s_m[wid] = m; s_s[wid] = s; }
    ((float4*)s_r[wid])[lane] = racc;
    __syncthreads();

    // combine 8 per-warp partials -> per-chunk partial
    if (tid < 128) {
        float M = -3.4e38f;
        #pragma unroll
        for (int w = 0; w < 8; ++w)
            if (s_s[w] > 0.f && s_m[w] > M) M = s_m[w];
        float S = 0.f, rs = 0.f;
        #pragma unroll
        for (int w = 0; w < 8; ++w) {
            if (s_s[w] > 0.f) {
                float sc = __expf(s_m[w] - M);
                S  += s_s[w] * sc;
                rs += s_r[w][tid] * sc;
            }
        }
        g_pr[b * DD + tid] = rs;
        if (tid == 0) { g_pm[b] = M; g_ps[b] = S; }
    }
}

// ---------------- fused: combine partials -> r, GEMM, activation -------------
__global__ __launch_bounds__(256) void lstm_kernel() {
    __shared__ float s_in[8][256];     // [h | r]
    __shared__ float s_gate[8][512];
    __shared__ float s_scale[8][CHUNKS];
    __shared__ float s_S[8];

    int g0 = blockIdx.x * 8;
    int tid = threadIdx.x;

    if (tid < 8) {
        int g = g0 + tid;
        float M = -3.4e38f;
        #pragma unroll
        for (int w = 0; w < CHUNKS; ++w) {
            float sw = g_ps[g * CHUNKS + w], mw = g_pm[g * CHUNKS + w];
            if (sw > 0.f && mw > M) M = mw;
        }
        float S = 0.f;
        #pragma unroll
        for (int w = 0; w < CHUNKS; ++w) {
            float sw = g_ps[g * CHUNKS + w];
            float sc = (sw > 0.f) ? __expf(g_pm[g * CHUNKS + w] - M) : 0.f;
            s_scale[tid][w] = sc;
            S += sw * sc;
        }
        s_S[tid] = S;
    }
    for (int it = tid; it < 8 * 128; it += 256) {
        int g = it >> 7, c = it & 127;
        s_in[g][c] = g_h[(g0 + g) * DD + c];
    }
    __syncthreads();
    for (int it = tid; it < 8 * 128; it += 256) {
        int g = it >> 7, c = it & 127;
        float rs = 0.f;
        #pragma unroll
        for (int w = 0; w < CHUNKS; ++w)
            rs += s_scale[g][w] * g_pr[((g0 + g) * CHUNKS + w) * DD + c];
        float S = s_S[g];
        s_in[g][128 + c] = (S > 0.f) ? rs / (S + 1e-16f) : 0.f;
    }
    __syncthreads();
    float acc0[8], acc1[8];
    #pragma unroll
    for (int t = 0; t < 8; ++t) { acc0[t] = 0.f; acc1[t] = 0.f; }
    const float4* w0 = (const float4*)(g_Weff + tid * 256);
    const float4* w1 = (const float4*)(g_Weff + (tid + 256) * 256);
    #pragma unroll 4
    for (int k4 = 0; k4 < 64; ++k4) {
        float4 wa = w0[k4], wb = w1[k4];
        #pragma unroll
        for (int t = 0; t < 8; ++t) {
            float4 iv = *(const float4*)&s_in[t][k4 * 4];
            acc0[t] += wa.x * iv.x + wa.y * iv.y + wa.z * iv.z + wa.w * iv.w;
            acc1[t] += wb.x * iv.x + wb.y * iv.y + wb.z * iv.z + wb.w * iv.w;
        }
    }
    float b0 = g_bias[tid], b1 = g_bias[tid + 256];
    #pragma unroll
    for (int t = 0; t < 8; ++t) {
        s_gate[t][tid]       = acc0[t] + b0;
        s_gate[t][tid + 256] = acc1[t] + b1;
    }
    __syncthreads();
    for (int it = tid; it < 8 * 128; it += 256) {
        int g = it >> 7, c = it & 127;
        float gi = s_gate[g][c];
        float gf = s_gate[g][c + 128];
        float gg = s_gate[g][c + 256];
        float go = s_gate[g][c + 384];
        int idx = (g0 + g) * DD + c;
        float cn = sigf(gf) * g_c[idx] + sigf(gi) * tanhf(gg);
        float hn = sigf(go) * tanhf(cn);
        g_c[idx] = cn;
        g_h[idx] = hn;
    }
}

// ---------------- final combine: r from partials, write [q, r] ---------------
__global__ __launch_bounds__(128) void combine_out_kernel(float* __restrict__ out) {
    int g = blockIdx.x, tid = threadIdx.x;
    float M = -3.4e38f;
    #pragma unroll
    for (int w = 0; w < CHUNKS; ++w) {
        float sw = g_ps[g * CHUNKS + w], mw = g_pm[g * CHUNKS + w];
        if (sw > 0.f && mw > M) M = mw;
    }
    float S = 0.f, rs = 0.f;
    #pragma unroll
    for (int w = 0; w < CHUNKS; ++w) {
        float sw = g_ps[g * CHUNKS + w];
        if (sw > 0.f) {
            float sc = __expf(g_pm[g * CHUNKS + w] - M);
            S  += sw * sc;
            rs += g_pr[(g * CHUNKS + w) * DD + tid] * sc;
        }
    }
    float rf = (S > 0.f) ? rs / (S + 1e-16f) : 0.f;
    out[g * 2 * DD + tid]      = g_h[g * DD + tid];  // q
    out[g * 2 * DD + DD + tid] = rf;                 // r
}

// ---------------- launch (8 kernels) ----------------
extern "C" void kernel_launch(void* const* d_in, const int* in_sizes, int n_in,
                              void* d_out, int out_size) {
    const float* x    = (const float*)d_in[0];
    const void*  bi   = d_in[1];
    const float* W_ih = (const float*)d_in[2];
    const float* W_hh = (const float*)d_in[3];
    const float* b_ih = (const float*)d_in[4];
    const float* b_hh = (const float*)d_in[5];
    float* out = (float*)d_out;

    setup_kernel<<<512, 256>>>(W_ih, W_hh, b_ih, b_hh, (const int*)bi);
    offsets_kernel<<<(NN / 8 + 255) / 256, 256>>>(bi);
    attn_kernel<<<NPART, 256>>>(x);
    lstm_kernel<<<BB / 8, 256>>>();
    attn_kernel<<<NPART, 256>>>(x);
    lstm_kernel<<<BB / 8, 256>>>();
    attn_kernel<<<NPART, 256>>>(x);
    combine_out_kernel<<<BB, 128>>>(out);
}